// round 5
// baseline (speedup 1.0000x reference)
#include <cuda_runtime.h>
#include <cuda_bf16.h>
#include <cstdint>

#define HID 128
#define IN_DIM 257
#define TE 8            // edges per block pass
#define BLOCK 256
#define INP_STRIDE 260  // pad so float4 rows stay 16B-aligned (260*4=1040)

struct Smem {
    float w1[IN_DIM * HID];   // 131584 B
    float w2[HID * HID];      //  65536 B
    float w3[HID];
    float b1[HID];
    float b2[HID];
    float inp[TE][INP_STRIDE];
    float x1[TE][HID];
    float phi[TE];
    int   row[TE];
};

__device__ __forceinline__ float silu(float x) {
    return x / (1.0f + __expf(-x));
}

__global__ void zero_kernel(float* out, int n) {
    int i = blockIdx.x * blockDim.x + threadIdx.x;
    if (i < n) out[i] = 0.0f;
}

__global__ __launch_bounds__(BLOCK, 1)
void edge_kernel(const float* __restrict__ h,
                 const int*   __restrict__ edge_index,
                 const float* __restrict__ coord_diff,
                 const float* __restrict__ edge_attr,
                 const float* __restrict__ edge_mask,
                 const float* __restrict__ W1, const float* __restrict__ b1,
                 const float* __restrict__ W2, const float* __restrict__ b2,
                 const float* __restrict__ W3,
                 float* __restrict__ agg,   // [N_NODES*3], pre-zeroed
                 int E)
{
    extern __shared__ char smem_raw[];
    Smem& s = *reinterpret_cast<Smem*>(smem_raw);

    const int tid = threadIdx.x;

    // ---- Stage weights into SMEM (once per block) ----
    for (int i = tid; i < IN_DIM * HID; i += BLOCK) s.w1[i] = W1[i];
    for (int i = tid; i < HID * HID;   i += BLOCK) s.w2[i] = W2[i];
    if (tid < HID) {
        s.w3[tid] = W3[tid];
        s.b1[tid] = b1[tid];
        s.b2[tid] = b2[tid];
    }
    __syncthreads();

    const int nGroups = (E + TE - 1) / TE;
    const int j  = tid & (HID - 1);   // output neuron
    const int eh = tid >> 7;          // 0 or 1: which half of the 8 edges
    const int e0 = eh * 4;
    const int lane = tid & 31;

    for (int g = blockIdx.x; g < nGroups; g += gridDim.x) {
        const int base = g * TE;

        // ---- Stage A: gather inputs for TE edges ----
        if (tid < TE) {
            s.phi[tid] = 0.0f;
            int edge = base + tid;
            s.row[tid] = (edge < E) ? edge_index[edge] : 0;
        }
        {
            const int e = tid >> 5;          // 0..7
            const int edge = base + e;
            if (edge < E) {
                const int r = edge_index[edge];
                const int c = edge_index[E + edge];
                const float4* hr = reinterpret_cast<const float4*>(h + (size_t)r * HID);
                const float4* hc = reinterpret_cast<const float4*>(h + (size_t)c * HID);
                float4* d0 = reinterpret_cast<float4*>(&s.inp[e][0]);
                float4* d1 = reinterpret_cast<float4*>(&s.inp[e][HID]);
                d0[lane] = hr[lane];
                d1[lane] = hc[lane];
                if (lane == 0) s.inp[e][2 * HID] = edge_attr[edge];
            }
        }
        __syncthreads();

        // ---- Stage B: layer 1, x1 = silu(inp @ W1 + b1) ----
        {
            float acc[4];
            #pragma unroll
            for (int k = 0; k < 4; ++k) acc[k] = s.b1[j];

            #pragma unroll 2
            for (int i = 0; i < 256; i += 4) {
                const float w0 = s.w1[(i + 0) * HID + j];
                const float w1v = s.w1[(i + 1) * HID + j];
                const float w2v = s.w1[(i + 2) * HID + j];
                const float w3v = s.w1[(i + 3) * HID + j];
                #pragma unroll
                for (int k = 0; k < 4; ++k) {
                    float4 a = *reinterpret_cast<const float4*>(&s.inp[e0 + k][i]);
                    acc[k] = fmaf(a.x, w0,  acc[k]);
                    acc[k] = fmaf(a.y, w1v, acc[k]);
                    acc[k] = fmaf(a.z, w2v, acc[k]);
                    acc[k] = fmaf(a.w, w3v, acc[k]);
                }
            }
            const float wl = s.w1[256 * HID + j];
            #pragma unroll
            for (int k = 0; k < 4; ++k) {
                acc[k] = fmaf(s.inp[e0 + k][256], wl, acc[k]);
                s.x1[e0 + k][j] = silu(acc[k]);
            }
        }
        __syncthreads();

        // ---- Stage C: layer 2 + phi reduction ----
        {
            float acc[4];
            #pragma unroll
            for (int k = 0; k < 4; ++k) acc[k] = s.b2[j];

            #pragma unroll 2
            for (int i = 0; i < HID; i += 4) {
                const float w0 = s.w2[(i + 0) * HID + j];
                const float w1v = s.w2[(i + 1) * HID + j];
                const float w2v = s.w2[(i + 2) * HID + j];
                const float w3v = s.w2[(i + 3) * HID + j];
                #pragma unroll
                for (int k = 0; k < 4; ++k) {
                    float4 a = *reinterpret_cast<const float4*>(&s.x1[e0 + k][i]);
                    acc[k] = fmaf(a.x, w0,  acc[k]);
                    acc[k] = fmaf(a.y, w1v, acc[k]);
                    acc[k] = fmaf(a.z, w2v, acc[k]);
                    acc[k] = fmaf(a.w, w3v, acc[k]);
                }
            }
            const float w3j = s.w3[j];
            #pragma unroll
            for (int k = 0; k < 4; ++k) {
                float p = silu(acc[k]) * w3j;
                #pragma unroll
                for (int o = 16; o > 0; o >>= 1)
                    p += __shfl_xor_sync(0xffffffffu, p, o);
                if (lane == 0) atomicAdd(&s.phi[e0 + k], p);
            }
        }
        __syncthreads();

        // ---- Stage D: trans = coord_diff * phi * edge_mask; scatter ----
        if (tid < TE * 3) {
            const int e = tid / 3;
            const int d = tid % 3;
            const int edge = base + e;
            if (edge < E) {
                const float tr = coord_diff[edge * 3 + d] * s.phi[e] * edge_mask[edge];
                atomicAdd(&agg[(size_t)s.row[e] * 3 + d], tr);
            }
        }
        __syncthreads();   // protect s.phi / s.inp before next group's writes
    }
}

__global__ void finalize_kernel(float* __restrict__ out,
                                const float* __restrict__ coord,
                                const float* __restrict__ node_mask,
                                int n3)
{
    int i = blockIdx.x * blockDim.x + threadIdx.x;
    if (i < n3) {
        float agg = out[i] * (1.0f / 100.0f);
        out[i] = (coord[i] + agg) * node_mask[i / 3];
    }
}

extern "C" void kernel_launch(void* const* d_in, const int* in_sizes, int n_in,
                              void* d_out, int out_size)
{
    const float* h          = (const float*)d_in[0];
    const float* coord      = (const float*)d_in[1];
    const int*   edge_index = (const int*)  d_in[2];
    const float* coord_diff = (const float*)d_in[3];
    // d_in[4] = coord_cross (unused by reference output path)
    const float* edge_attr  = (const float*)d_in[5];
    const float* node_mask  = (const float*)d_in[6];
    const float* edge_mask  = (const float*)d_in[7];
    const float* W1         = (const float*)d_in[8];
    const float* b1         = (const float*)d_in[9];
    const float* W2         = (const float*)d_in[10];
    const float* b2         = (const float*)d_in[11];
    const float* W3         = (const float*)d_in[12];
    float* out = (float*)d_out;

    const int E  = in_sizes[5];        // edge_attr count == N_EDGES
    const int n3 = out_size;           // N_NODES * 3

    static const size_t SMEM_BYTES = sizeof(Smem);
    cudaFuncSetAttribute(edge_kernel,
                         cudaFuncAttributeMaxDynamicSharedMemorySize,
                         (int)SMEM_BYTES);

    // 1) zero agg accumulator (d_out is poisoned)
    zero_kernel<<<(n3 + 255) / 256, 256>>>(out, n3);

    // 2) edge MLP + scatter
    const int nGroups = (E + TE - 1) / TE;
    int grid = nGroups < 152 ? nGroups : 152;
    edge_kernel<<<grid, BLOCK, SMEM_BYTES>>>(
        h, edge_index, coord_diff, edge_attr, edge_mask,
        W1, b1, W2, b2, W3, out, E);

    // 3) finalize: (coord + agg/100) * node_mask
    finalize_kernel<<<(n3 + 255) / 256, 256>>>(out, coord, node_mask, n3);
}

// round 8
// speedup vs baseline: 5.6968x; 5.6968x over previous
#include <cuda_runtime.h>
#include <cuda_bf16.h>
#include <cstdint>

#define HID 128
#define TILE_M 128          // edges per tile
#define BLOCK 256           // 8 warps
#define A_STRIDE 280        // bf16 elems per A row (560 B) -> conflict-free ldmatrix
#define W_STRIDE 136        // bf16 elems per W/X1 row (272 B) -> conflict-free ldmatrix
#define K1 272              // padded in_dim (257 -> 272, multiple of 16)
#define GRID_SMS 152

struct SmemT {
    __nv_bfloat16 A[TILE_M * A_STRIDE];     //  71680 B  input tile [128 x 272(+pad)]
    __nv_bfloat16 W1b[K1 * W_STRIDE];       //  73984 B  W1 [272 x 128(+pad)]
    __nv_bfloat16 W2b[HID * W_STRIDE];      //  34816 B  W2 [128 x 128(+pad)]
    __nv_bfloat16 X1[TILE_M * W_STRIDE];    //  34816 B  layer-1 activations
    float b1s[HID];
    float b2s[HID];
    float w3s[HID];
    float phi[TILE_M];
    int   rowi[TILE_M];
    int   coli[TILE_M];
};   // ~219 KB

__device__ __forceinline__ float silu(float x) {
    return x / (1.0f + __expf(-x));
}

__device__ __forceinline__ void ldsm_x4(uint32_t& r0, uint32_t& r1, uint32_t& r2, uint32_t& r3,
                                        uint32_t addr) {
    asm volatile("ldmatrix.sync.aligned.m8n8.x4.shared.b16 {%0,%1,%2,%3}, [%4];"
                 : "=r"(r0), "=r"(r1), "=r"(r2), "=r"(r3) : "r"(addr));
}

__device__ __forceinline__ void ldsm_x4_trans(uint32_t& r0, uint32_t& r1, uint32_t& r2, uint32_t& r3,
                                              uint32_t addr) {
    asm volatile("ldmatrix.sync.aligned.m8n8.x4.trans.shared.b16 {%0,%1,%2,%3}, [%4];"
                 : "=r"(r0), "=r"(r1), "=r"(r2), "=r"(r3) : "r"(addr));
}

__device__ __forceinline__ void mma_bf16(float* c, const uint32_t* a, const uint32_t* b) {
    asm volatile("mma.sync.aligned.m16n8k16.row.col.f32.bf16.bf16.f32 "
                 "{%0,%1,%2,%3}, {%4,%5,%6,%7}, {%8,%9}, {%0,%1,%2,%3};"
                 : "+f"(c[0]), "+f"(c[1]), "+f"(c[2]), "+f"(c[3])
                 : "r"(a[0]), "r"(a[1]), "r"(a[2]), "r"(a[3]), "r"(b[0]), "r"(b[1]));
}

__global__ void zero_kernel(float* out, int n) {
    int i = blockIdx.x * blockDim.x + threadIdx.x;
    if (i < n) out[i] = 0.0f;
}

__global__ __launch_bounds__(BLOCK, 1)
void edge_kernel(const float* __restrict__ h,
                 const int*   __restrict__ edge_index,
                 const float* __restrict__ coord_diff,
                 const float* __restrict__ edge_attr,
                 const float* __restrict__ edge_mask,
                 const float* __restrict__ W1, const float* __restrict__ b1,
                 const float* __restrict__ W2, const float* __restrict__ b2,
                 const float* __restrict__ W3,
                 float* __restrict__ agg,
                 int E)
{
    extern __shared__ char smem_raw[];
    SmemT& s = *reinterpret_cast<SmemT*>(smem_raw);

    const int tid  = threadIdx.x;
    const int wid  = tid >> 5;
    const int lane = tid & 31;

    // ---- One-time: stage weights (fp32 -> bf16) into SMEM ----
    for (int i = tid; i < K1 * HID; i += BLOCK) {
        int r = i >> 7, c = i & 127;
        float v = (r < 257) ? W1[r * HID + c] : 0.0f;
        s.W1b[r * W_STRIDE + c] = __float2bfloat16_rn(v);
    }
    for (int i = tid; i < HID * HID; i += BLOCK) {
        int r = i >> 7, c = i & 127;
        s.W2b[r * W_STRIDE + c] = __float2bfloat16_rn(W2[i]);
    }
    if (tid < HID) {
        s.b1s[tid] = b1[tid];
        s.b2s[tid] = b2[tid];
        s.w3s[tid] = W3[tid];
    }
    // Zero the K-padding columns of A (cols 256..271) once; they persist.
    for (int i = tid; i < TILE_M * 16; i += BLOCK) {
        int r = i >> 4, c = 256 + (i & 15);
        s.A[r * A_STRIDE + c] = __float2bfloat16_rn(0.0f);
    }
    __syncthreads();

    const uint32_t smA  = (uint32_t)__cvta_generic_to_shared(s.A);
    const uint32_t smW1 = (uint32_t)__cvta_generic_to_shared(s.W1b);
    const uint32_t smW2 = (uint32_t)__cvta_generic_to_shared(s.W2b);
    const uint32_t smX1 = (uint32_t)__cvta_generic_to_shared(s.X1);

    const int mrow = (wid & 3) * 32;   // this warp's 32 output rows
    const int ncol = (wid >> 2) * 64;  // this warp's 64 output cols
    const int g    = lane >> 2;        // row group within fragment
    const int t4   = lane & 3;         // col pair within fragment

    const int nTiles = (E + TILE_M - 1) / TILE_M;

    for (int tile = blockIdx.x; tile < nTiles; tile += gridDim.x) {
        const int base = tile * TILE_M;

        // ---- Stage A0: edge indices, attr, phi reset ----
        if (tid < TILE_M) {
            int eg = base + tid;
            int r = 0, c = 0;
            float at = 0.0f;
            if (eg < E) {
                r  = edge_index[eg];
                c  = edge_index[E + eg];
                at = edge_attr[eg];
            }
            s.rowi[tid] = r;
            s.coli[tid] = c;
            s.phi[tid]  = 0.0f;
            s.A[tid * A_STRIDE + 256] = __float2bfloat16_rn(at);
        }
        __syncthreads();

        // ---- Gather: one warp loads one full node vector per iteration ----
        // 256 vectors (128 edges x {row,col}); coalesced 512B per warp-LDG.
        for (int v = wid; v < 2 * TILE_M; v += 8) {
            const int e  = v >> 1;
            const int hf = v & 1;
            const int node = hf ? s.coli[e] : s.rowi[e];
            const float4* src = reinterpret_cast<const float4*>(h + (size_t)node * HID);
            float4 f = src[lane];
            __nv_bfloat162 p0 = __floats2bfloat162_rn(f.x, f.y);
            __nv_bfloat162 p1 = __floats2bfloat162_rn(f.z, f.w);
            __nv_bfloat162* dst = reinterpret_cast<__nv_bfloat162*>(
                &s.A[e * A_STRIDE + hf * HID + lane * 4]);
            dst[0] = p0;
            dst[1] = p1;
        }
        __syncthreads();

        // ---- GEMM1: X1 = silu(A @ W1 + b1), M=128 N=128 K=272 ----
        {
            float acc[2][8][4];
            #pragma unroll
            for (int mt = 0; mt < 2; ++mt)
                #pragma unroll
                for (int nt = 0; nt < 8; ++nt)
                    #pragma unroll
                    for (int q = 0; q < 4; ++q) acc[mt][nt][q] = 0.0f;

            for (int k0 = 0; k0 < K1; k0 += 16) {
                uint32_t a[2][4];
                #pragma unroll
                for (int mt = 0; mt < 2; ++mt) {
                    uint32_t addr = smA + (((mrow + mt * 16 + (lane & 15)) * A_STRIDE)
                                           + k0 + 8 * (lane >> 4)) * 2;
                    ldsm_x4(a[mt][0], a[mt][1], a[mt][2], a[mt][3], addr);
                }
                uint32_t b[8][2];
                #pragma unroll
                for (int nb = 0; nb < 4; ++nb) {
                    uint32_t addr = smW1 + (((k0 + (lane & 15)) * W_STRIDE)
                                            + ncol + nb * 16 + 8 * (lane >> 4)) * 2;
                    uint32_t r0, r1, r2, r3;
                    ldsm_x4_trans(r0, r1, r2, r3, addr);
                    b[nb * 2][0] = r0; b[nb * 2][1] = r1;
                    b[nb * 2 + 1][0] = r2; b[nb * 2 + 1][1] = r3;
                }
                #pragma unroll
                for (int mt = 0; mt < 2; ++mt)
                    #pragma unroll
                    for (int nt = 0; nt < 8; ++nt)
                        mma_bf16(acc[mt][nt], a[mt], b[nt]);
            }

            // Epilogue: + b1, silu, store bf16 X1
            #pragma unroll
            for (int mt = 0; mt < 2; ++mt) {
                #pragma unroll
                for (int nt = 0; nt < 8; ++nt) {
                    const int cc = ncol + nt * 8 + t4 * 2;
                    const float bb0 = s.b1s[cc], bb1 = s.b1s[cc + 1];
                    const int r0 = mrow + mt * 16 + g;
                    const int r1 = r0 + 8;
                    float v00 = silu(acc[mt][nt][0] + bb0);
                    float v01 = silu(acc[mt][nt][1] + bb1);
                    float v10 = silu(acc[mt][nt][2] + bb0);
                    float v11 = silu(acc[mt][nt][3] + bb1);
                    *reinterpret_cast<__nv_bfloat162*>(&s.X1[r0 * W_STRIDE + cc]) =
                        __floats2bfloat162_rn(v00, v01);
                    *reinterpret_cast<__nv_bfloat162*>(&s.X1[r1 * W_STRIDE + cc]) =
                        __floats2bfloat162_rn(v10, v11);
                }
            }
        }
        __syncthreads();

        // ---- GEMM2: X2 = silu(X1 @ W2 + b2); phi = X2 @ W3  (fused) ----
        {
            float acc[2][8][4];
            #pragma unroll
            for (int mt = 0; mt < 2; ++mt)
                #pragma unroll
                for (int nt = 0; nt < 8; ++nt)
                    #pragma unroll
                    for (int q = 0; q < 4; ++q) acc[mt][nt][q] = 0.0f;

            for (int k0 = 0; k0 < HID; k0 += 16) {
                uint32_t a[2][4];
                #pragma unroll
                for (int mt = 0; mt < 2; ++mt) {
                    uint32_t addr = smX1 + (((mrow + mt * 16 + (lane & 15)) * W_STRIDE)
                                            + k0 + 8 * (lane >> 4)) * 2;
                    ldsm_x4(a[mt][0], a[mt][1], a[mt][2], a[mt][3], addr);
                }
                uint32_t b[8][2];
                #pragma unroll
                for (int nb = 0; nb < 4; ++nb) {
                    uint32_t addr = smW2 + (((k0 + (lane & 15)) * W_STRIDE)
                                            + ncol + nb * 16 + 8 * (lane >> 4)) * 2;
                    uint32_t r0, r1, r2, r3;
                    ldsm_x4_trans(r0, r1, r2, r3, addr);
                    b[nb * 2][0] = r0; b[nb * 2][1] = r1;
                    b[nb * 2 + 1][0] = r2; b[nb * 2 + 1][1] = r3;
                }
                #pragma unroll
                for (int mt = 0; mt < 2; ++mt)
                    #pragma unroll
                    for (int nt = 0; nt < 8; ++nt)
                        mma_bf16(acc[mt][nt], a[mt], b[nt]);
            }

            // Epilogue: silu, * W3, reduce over this warp's 64 cols -> phi
            float p[4] = {0.0f, 0.0f, 0.0f, 0.0f};  // [mt*2 + rowhalf]
            #pragma unroll
            for (int mt = 0; mt < 2; ++mt) {
                #pragma unroll
                for (int nt = 0; nt < 8; ++nt) {
                    const int cc = ncol + nt * 8 + t4 * 2;
                    const float bb0 = s.b2s[cc], bb1 = s.b2s[cc + 1];
                    const float w0 = s.w3s[cc],  w1 = s.w3s[cc + 1];
                    p[mt * 2 + 0] += silu(acc[mt][nt][0] + bb0) * w0
                                   + silu(acc[mt][nt][1] + bb1) * w1;
                    p[mt * 2 + 1] += silu(acc[mt][nt][2] + bb0) * w0
                                   + silu(acc[mt][nt][3] + bb1) * w1;
                }
            }
            #pragma unroll
            for (int q = 0; q < 4; ++q) {
                p[q] += __shfl_xor_sync(0xffffffffu, p[q], 1);
                p[q] += __shfl_xor_sync(0xffffffffu, p[q], 2);
            }
            if (t4 == 0) {
                #pragma unroll
                for (int mt = 0; mt < 2; ++mt) {
                    atomicAdd(&s.phi[mrow + mt * 16 + g],     p[mt * 2 + 0]);
                    atomicAdd(&s.phi[mrow + mt * 16 + g + 8], p[mt * 2 + 1]);
                }
            }
        }
        __syncthreads();

        // ---- Scatter: trans = coord_diff * phi * edge_mask -> agg ----
        if (tid < TILE_M) {
            const int eg = base + tid;
            if (eg < E) {
                const float ph = s.phi[tid] * edge_mask[eg];
                const int r = s.rowi[tid];
                const float cdx = coord_diff[eg * 3 + 0];
                const float cdy = coord_diff[eg * 3 + 1];
                const float cdz = coord_diff[eg * 3 + 2];
                atomicAdd(&agg[(size_t)r * 3 + 0], cdx * ph);
                atomicAdd(&agg[(size_t)r * 3 + 1], cdy * ph);
                atomicAdd(&agg[(size_t)r * 3 + 2], cdz * ph);
            }
        }
        __syncthreads();  // protect A/phi before next tile overwrites
    }
}

__global__ void finalize_kernel(float* __restrict__ out,
                                const float* __restrict__ coord,
                                const float* __restrict__ node_mask,
                                int n3)
{
    int i = blockIdx.x * blockDim.x + threadIdx.x;
    if (i < n3) {
        float agg = out[i] * (1.0f / 100.0f);
        out[i] = (coord[i] + agg) * node_mask[i / 3];
    }
}

extern "C" void kernel_launch(void* const* d_in, const int* in_sizes, int n_in,
                              void* d_out, int out_size)
{
    const float* h          = (const float*)d_in[0];
    const float* coord      = (const float*)d_in[1];
    const int*   edge_index = (const int*)  d_in[2];
    const float* coord_diff = (const float*)d_in[3];
    // d_in[4] = coord_cross (unused)
    const float* edge_attr  = (const float*)d_in[5];
    const float* node_mask  = (const float*)d_in[6];
    const float* edge_mask  = (const float*)d_in[7];
    const float* W1         = (const float*)d_in[8];
    const float* b1         = (const float*)d_in[9];
    const float* W2         = (const float*)d_in[10];
    const float* b2         = (const float*)d_in[11];
    const float* W3         = (const float*)d_in[12];
    float* out = (float*)d_out;

    const int E  = in_sizes[5];
    const int n3 = out_size;

    static const int SMEM_BYTES = (int)sizeof(SmemT);
    cudaFuncSetAttribute(edge_kernel,
                         cudaFuncAttributeMaxDynamicSharedMemorySize,
                         SMEM_BYTES);

    zero_kernel<<<(n3 + 255) / 256, 256>>>(out, n3);

    const int nTiles = (E + TILE_M - 1) / TILE_M;
    int grid = nTiles < GRID_SMS ? nTiles : GRID_SMS;
    edge_kernel<<<grid, BLOCK, SMEM_BYTES>>>(
        h, edge_index, coord_diff, edge_attr, edge_mask,
        W1, b1, W2, b2, W3, out, E);

    finalize_kernel<<<(n3 + 255) / 256, 256>>>(out, coord, node_mask, n3);
}

// round 12
// speedup vs baseline: 10.7935x; 1.8947x over previous
#include <cuda_runtime.h>
#include <cuda_bf16.h>
#include <cstdint>

#define HID 128
#define TILE_M 128          // edges per tile
#define BLOCK 512           // 16 warps
#define A_STRIDE 280        // bf16/row (560 B): 140 words ≡ 12 mod 32 -> conflict-free ldmatrix
#define W_STRIDE 136        // bf16/row (272 B): 68 words ≡ 4 mod 32 -> conflict-free ldmatrix
#define K1 272              // padded in_dim (257 -> 272)
#define GRID_SMS 152
#define N_NODES_MAX 50000

__device__ __nv_bfloat16 g_hbf[N_NODES_MAX * HID];   // 12.8 MB bf16 copy of h

struct SmemT {
    __nv_bfloat16 A[TILE_M * A_STRIDE];     // 71680 B  input tile
    __nv_bfloat16 W1b[K1 * W_STRIDE];       // 73984 B
    __nv_bfloat16 W2b[HID * W_STRIDE];      // 34816 B
    __nv_bfloat16 X1[TILE_M * W_STRIDE];    // 34816 B
    float b1s[HID];
    float b2s[HID];
    float w3s[HID];
    float phiP[4][TILE_M];                  // per-colgroup partials (no atomics)
    int   rowi[2][TILE_M];
    int   coli[2][TILE_M];
};   // ~221 KB

__device__ __forceinline__ float silu(float x) { return x / (1.0f + __expf(-x)); }

__device__ __forceinline__ void ldsm_x4(uint32_t& r0, uint32_t& r1, uint32_t& r2, uint32_t& r3,
                                        uint32_t addr) {
    asm volatile("ldmatrix.sync.aligned.m8n8.x4.shared.b16 {%0,%1,%2,%3}, [%4];"
                 : "=r"(r0), "=r"(r1), "=r"(r2), "=r"(r3) : "r"(addr));
}
__device__ __forceinline__ void ldsm_x4_trans(uint32_t& r0, uint32_t& r1, uint32_t& r2, uint32_t& r3,
                                              uint32_t addr) {
    asm volatile("ldmatrix.sync.aligned.m8n8.x4.trans.shared.b16 {%0,%1,%2,%3}, [%4];"
                 : "=r"(r0), "=r"(r1), "=r"(r2), "=r"(r3) : "r"(addr));
}
__device__ __forceinline__ void mma_bf16(float* c, const uint32_t* a, const uint32_t* b) {
    asm volatile("mma.sync.aligned.m16n8k16.row.col.f32.bf16.bf16.f32 "
                 "{%0,%1,%2,%3}, {%4,%5,%6,%7}, {%8,%9}, {%0,%1,%2,%3};"
                 : "+f"(c[0]), "+f"(c[1]), "+f"(c[2]), "+f"(c[3])
                 : "r"(a[0]), "r"(a[1]), "r"(a[2]), "r"(a[3]), "r"(b[0]), "r"(b[1]));
}

#define CP_ASYNC16(dst, src) \
    asm volatile("cp.async.cg.shared.global [%0], [%1], 16;" :: "r"(dst), "l"(src))
#define CP_COMMIT()  asm volatile("cp.async.commit_group;" ::: "memory")
#define CP_WAIT0()   asm volatile("cp.async.wait_group 0;" ::: "memory")

__global__ void convert_h_kernel(const float* __restrict__ h, int n4) {
    int i = blockIdx.x * blockDim.x + threadIdx.x;
    if (i < n4) {
        float4 f = reinterpret_cast<const float4*>(h)[i];
        __nv_bfloat162* dst = reinterpret_cast<__nv_bfloat162*>(g_hbf) + i * 2;
        dst[0] = __floats2bfloat162_rn(f.x, f.y);
        dst[1] = __floats2bfloat162_rn(f.z, f.w);
    }
}

__global__ void zero_kernel(float* out, int n) {
    int i = blockIdx.x * blockDim.x + threadIdx.x;
    if (i < n) out[i] = 0.0f;
}

// Issue cp.async gather of one tile's A operand (256 node rows of 256 B).
__device__ __forceinline__ void gather_tile(SmemT& s, uint32_t smA, int p,
                                            int wid, int lane) {
    const int rbase = wid * 16;
    const int half = lane >> 4;       // 0/1: which of the 2 rows this step
    const int cb = lane & 15;         // 16B chunk within row
    #pragma unroll
    for (int i = 0; i < 8; ++i) {
        const int r = rbase + i * 2 + half;   // 0..255
        const int e = r >> 1;
        const int hf = r & 1;
        const int node = hf ? s.coli[p][e] : s.rowi[p][e];
        const __nv_bfloat16* src = g_hbf + (size_t)node * HID + cb * 8;
        const uint32_t dst = smA + (uint32_t)(e * A_STRIDE + hf * HID + cb * 8) * 2;
        CP_ASYNC16(dst, src);
    }
    CP_COMMIT();
}

__global__ __launch_bounds__(BLOCK, 1)
void edge_kernel(const int*   __restrict__ edge_index,
                 const float* __restrict__ coord_diff,
                 const float* __restrict__ edge_attr,
                 const float* __restrict__ edge_mask,
                 const float* __restrict__ W1, const float* __restrict__ b1,
                 const float* __restrict__ W2, const float* __restrict__ b2,
                 const float* __restrict__ W3,
                 float* __restrict__ agg,
                 int E)
{
    extern __shared__ char smem_raw[];
    SmemT& s = *reinterpret_cast<SmemT*>(smem_raw);

    const int tid  = threadIdx.x;
    const int wid  = tid >> 5;
    const int lane = tid & 31;

    // ---- One-time: stage weights (fp32 -> bf16) ----
    for (int i = tid; i < K1 * HID; i += BLOCK) {
        int r = i >> 7, c = i & 127;
        float v = (r < 257) ? W1[r * HID + c] : 0.0f;
        s.W1b[r * W_STRIDE + c] = __float2bfloat16_rn(v);
    }
    for (int i = tid; i < HID * HID; i += BLOCK) {
        int r = i >> 7, c = i & 127;
        s.W2b[r * W_STRIDE + c] = __float2bfloat16_rn(W2[i]);
    }
    if (tid < HID) { s.b1s[tid] = b1[tid]; s.b2s[tid] = b2[tid]; s.w3s[tid] = W3[tid]; }
    // Zero K-padding cols 257..271 (persist forever; col 256 = attr set per tile)
    for (int i = tid; i < TILE_M * 15; i += BLOCK) {
        int r = i / 15, c = 257 + (i % 15);
        s.A[r * A_STRIDE + c] = __float2bfloat16_rn(0.0f);
    }

    const uint32_t smA  = (uint32_t)__cvta_generic_to_shared(s.A);
    const uint32_t smW1 = (uint32_t)__cvta_generic_to_shared(s.W1b);
    const uint32_t smW2 = (uint32_t)__cvta_generic_to_shared(s.W2b);
    const uint32_t smX1 = (uint32_t)__cvta_generic_to_shared(s.X1);

    const int mrow = (wid & 3) * 32;       // 32 output rows per warp
    const int ncol = (wid >> 2) * 32;      // 32 output cols per warp
    const int cg   = wid >> 2;             // col group 0..3
    const int g    = lane >> 2;
    const int t4   = lane & 3;

    const int nTiles = (E + TILE_M - 1) / TILE_M;

    // ---- Prologue: indices + attr for first tile, then async gather ----
    const int tile0 = blockIdx.x;
    if (tid < TILE_M && tile0 < nTiles) {
        int eg = tile0 * TILE_M + tid;
        int r = 0, c = 0; float at = 0.0f;
        if (eg < E) { r = edge_index[eg]; c = edge_index[E + eg]; at = edge_attr[eg]; }
        s.rowi[0][tid] = r; s.coli[0][tid] = c;
        s.A[tid * A_STRIDE + 256] = __float2bfloat16_rn(at);
    }
    __syncthreads();
    if (tile0 < nTiles) gather_tile(s, smA, 0, wid, lane);

    int p = 0;
    for (int tile = tile0; tile < nTiles; tile += gridDim.x) {
        CP_WAIT0();
        __syncthreads();                    // A + indices + attr for this tile ready

        // ---- Prefetch next tile's indices (LDG hidden under GEMM1) ----
        const int ntile = tile + gridDim.x;
        const bool hasNext = ntile < nTiles;
        float nat = 0.0f;
        if (tid < TILE_M) {
            int nr = 0, nc2 = 0;
            if (hasNext) {
                int eg = ntile * TILE_M + tid;
                if (eg < E) { nr = edge_index[eg]; nc2 = edge_index[E + eg]; nat = edge_attr[eg]; }
            }
            s.rowi[p ^ 1][tid] = nr; s.coli[p ^ 1][tid] = nc2;
        }

        // ---- GEMM1: X1 = silu(A @ W1 + b1)  [128x128, K=272] ----
        {
            float acc[2][4][4];
            #pragma unroll
            for (int mt = 0; mt < 2; ++mt)
                #pragma unroll
                for (int nt = 0; nt < 4; ++nt)
                    #pragma unroll
                    for (int q = 0; q < 4; ++q) acc[mt][nt][q] = 0.0f;

            for (int k0 = 0; k0 < K1; k0 += 16) {
                uint32_t a[2][4];
                #pragma unroll
                for (int mt = 0; mt < 2; ++mt) {
                    uint32_t addr = smA + (uint32_t)(((mrow + mt * 16 + (lane & 15)) * A_STRIDE)
                                                     + k0 + 8 * (lane >> 4)) * 2;
                    ldsm_x4(a[mt][0], a[mt][1], a[mt][2], a[mt][3], addr);
                }
                uint32_t b[4][2];
                #pragma unroll
                for (int nb = 0; nb < 2; ++nb) {
                    uint32_t addr = smW1 + (uint32_t)(((k0 + (lane & 15)) * W_STRIDE)
                                                      + ncol + nb * 16 + 8 * (lane >> 4)) * 2;
                    uint32_t r0, r1, r2, r3;
                    ldsm_x4_trans(r0, r1, r2, r3, addr);
                    b[nb * 2][0] = r0;     b[nb * 2][1] = r1;
                    b[nb * 2 + 1][0] = r2; b[nb * 2 + 1][1] = r3;
                }
                #pragma unroll
                for (int mt = 0; mt < 2; ++mt)
                    #pragma unroll
                    for (int nt = 0; nt < 4; ++nt)
                        mma_bf16(acc[mt][nt], a[mt], b[nt]);
            }

            #pragma unroll
            for (int mt = 0; mt < 2; ++mt)
                #pragma unroll
                for (int nt = 0; nt < 4; ++nt) {
                    const int cc = ncol + nt * 8 + t4 * 2;
                    const float bb0 = s.b1s[cc], bb1 = s.b1s[cc + 1];
                    const int r0 = mrow + mt * 16 + g, r1 = r0 + 8;
                    *reinterpret_cast<__nv_bfloat162*>(&s.X1[r0 * W_STRIDE + cc]) =
                        __floats2bfloat162_rn(silu(acc[mt][nt][0] + bb0),
                                              silu(acc[mt][nt][1] + bb1));
                    *reinterpret_cast<__nv_bfloat162*>(&s.X1[r1 * W_STRIDE + cc]) =
                        __floats2bfloat162_rn(silu(acc[mt][nt][2] + bb0),
                                              silu(acc[mt][nt][3] + bb1));
                }
        }
        __syncthreads();                    // X1 ready; A is now dead

        // ---- Overlap: launch next tile's gather under GEMM2 ----
        if (hasNext) {
            if (tid < TILE_M)
                s.A[tid * A_STRIDE + 256] = __float2bfloat16_rn(nat);
            gather_tile(s, smA, p ^ 1, wid, lane);
        }

        // ---- GEMM2: phi partials = sum_j silu(X1@W2+b2)[.,j] * W3[j] ----
        {
            float acc[2][4][4];
            #pragma unroll
            for (int mt = 0; mt < 2; ++mt)
                #pragma unroll
                for (int nt = 0; nt < 4; ++nt)
                    #pragma unroll
                    for (int q = 0; q < 4; ++q) acc[mt][nt][q] = 0.0f;

            for (int k0 = 0; k0 < HID; k0 += 16) {
                uint32_t a[2][4];
                #pragma unroll
                for (int mt = 0; mt < 2; ++mt) {
                    uint32_t addr = smX1 + (uint32_t)(((mrow + mt * 16 + (lane & 15)) * W_STRIDE)
                                                      + k0 + 8 * (lane >> 4)) * 2;
                    ldsm_x4(a[mt][0], a[mt][1], a[mt][2], a[mt][3], addr);
                }
                uint32_t b[4][2];
                #pragma unroll
                for (int nb = 0; nb < 2; ++nb) {
                    uint32_t addr = smW2 + (uint32_t)(((k0 + (lane & 15)) * W_STRIDE)
                                                      + ncol + nb * 16 + 8 * (lane >> 4)) * 2;
                    uint32_t r0, r1, r2, r3;
                    ldsm_x4_trans(r0, r1, r2, r3, addr);
                    b[nb * 2][0] = r0;     b[nb * 2][1] = r1;
                    b[nb * 2 + 1][0] = r2; b[nb * 2 + 1][1] = r3;
                }
                #pragma unroll
                for (int mt = 0; mt < 2; ++mt)
                    #pragma unroll
                    for (int nt = 0; nt < 4; ++nt)
                        mma_bf16(acc[mt][nt], a[mt], b[nt]);
            }

            float pr[4] = {0.0f, 0.0f, 0.0f, 0.0f};
            #pragma unroll
            for (int mt = 0; mt < 2; ++mt)
                #pragma unroll
                for (int nt = 0; nt < 4; ++nt) {
                    const int cc = ncol + nt * 8 + t4 * 2;
                    const float bb0 = s.b2s[cc], bb1 = s.b2s[cc + 1];
                    const float w0 = s.w3s[cc],  w1 = s.w3s[cc + 1];
                    pr[mt * 2 + 0] += silu(acc[mt][nt][0] + bb0) * w0
                                    + silu(acc[mt][nt][1] + bb1) * w1;
                    pr[mt * 2 + 1] += silu(acc[mt][nt][2] + bb0) * w0
                                    + silu(acc[mt][nt][3] + bb1) * w1;
                }
            #pragma unroll
            for (int q = 0; q < 4; ++q) {
                pr[q] += __shfl_xor_sync(0xffffffffu, pr[q], 1);
                pr[q] += __shfl_xor_sync(0xffffffffu, pr[q], 2);
            }
            if (t4 == 0) {
                #pragma unroll
                for (int mt = 0; mt < 2; ++mt) {
                    s.phiP[cg][mrow + mt * 16 + g]     = pr[mt * 2 + 0];
                    s.phiP[cg][mrow + mt * 16 + g + 8] = pr[mt * 2 + 1];
                }
            }
        }
        __syncthreads();                    // phi partials ready

        // ---- Scatter ----
        if (tid < TILE_M) {
            const int eg = tile * TILE_M + tid;
            if (eg < E) {
                const float ph = (s.phiP[0][tid] + s.phiP[1][tid] +
                                  s.phiP[2][tid] + s.phiP[3][tid]) * edge_mask[eg];
                const int r = s.rowi[p][tid];
                atomicAdd(&agg[(size_t)r * 3 + 0], coord_diff[eg * 3 + 0] * ph);
                atomicAdd(&agg[(size_t)r * 3 + 1], coord_diff[eg * 3 + 1] * ph);
                atomicAdd(&agg[(size_t)r * 3 + 2], coord_diff[eg * 3 + 2] * ph);
            }
        }
        p ^= 1;
        // no trailing sync needed: next-iteration writes touch only the opposite
        // index buffers / A (already being filled), ordered by the top wait+sync
    }
}

__global__ void finalize_kernel(float* __restrict__ out,
                                const float* __restrict__ coord,
                                const float* __restrict__ node_mask,
                                int n3)
{
    int i = blockIdx.x * blockDim.x + threadIdx.x;
    if (i < n3) {
        float agg = out[i] * (1.0f / 100.0f);
        out[i] = (coord[i] + agg) * node_mask[i / 3];
    }
}

extern "C" void kernel_launch(void* const* d_in, const int* in_sizes, int n_in,
                              void* d_out, int out_size)
{
    const float* h          = (const float*)d_in[0];
    const float* coord      = (const float*)d_in[1];
    const int*   edge_index = (const int*)  d_in[2];
    const float* coord_diff = (const float*)d_in[3];
    const float* edge_attr  = (const float*)d_in[5];
    const float* node_mask  = (const float*)d_in[6];
    const float* edge_mask  = (const float*)d_in[7];
    const float* W1         = (const float*)d_in[8];
    const float* b1         = (const float*)d_in[9];
    const float* W2         = (const float*)d_in[10];
    const float* b2         = (const float*)d_in[11];
    const float* W3         = (const float*)d_in[12];
    float* out = (float*)d_out;

    const int E  = in_sizes[5];
    const int n3 = out_size;
    const int nh4 = in_sizes[0] / 4;

    static const int SMEM_BYTES = (int)sizeof(SmemT);
    cudaFuncSetAttribute(edge_kernel,
                         cudaFuncAttributeMaxDynamicSharedMemorySize, SMEM_BYTES);

    convert_h_kernel<<<(nh4 + 255) / 256, 256>>>(h, nh4);
    zero_kernel<<<(n3 + 255) / 256, 256>>>(out, n3);

    const int nTiles = (E + TILE_M - 1) / TILE_M;
    int grid = nTiles < GRID_SMS ? nTiles : GRID_SMS;
    edge_kernel<<<grid, BLOCK, SMEM_BYTES>>>(
        edge_index, coord_diff, edge_attr, edge_mask,
        W1, b1, W2, b2, W3, out, E);

    finalize_kernel<<<(n3 + 255) / 256, 256>>>(out, coord, node_mask, n3);
}